// round 6
// baseline (speedup 1.0000x reference)
#include <cuda_runtime.h>
#include <cuda_bf16.h>
#include <cstdint>

// ---------------- problem constants ----------------
#define BATCH    8192
#define IN_DIM   512
#define NUM_TREE 64
#define NI       31
#define NL       32
#define ODIM     16

// ---------------- GEMM tiling ----------------
#define KP       1536        // packed K: [xh | xh | xl] vs [wh | wl | wh]
#define BM       128
#define BN       128         // 4 trees * 32 padded cols
#define BK       32
#define NKCH     (KP / BK)   // 48
#define NSTAGE   4
#define THREADS  256
#define APITCH   40          // bf16 elems per smem row (32 + 8 pad -> 80B stride)
#define NGRP     16          // N groups (16 * 128 = 2048 padded nodes)

#define STAGE_BYTES   20480u                 // A(10240) + B(10240)
#define SMEM_TOTAL    (STAGE_BYTES * NSTAGE) // 81920
// union region (reused after mainloop):
#define P_PITCH   133
#define UOFF_P    0u                         // float[128*133] = 68096 B
#define UOFF_LF   68096u                     // float[4*32*16] = 8192 B
#define UOFF_BIAS 76288u                     // float[128]     = 512 B

// ---------------- device scratch ----------------
__device__ __align__(16) __nv_bfloat16 g_A[(size_t)BATCH * KP];     // 25.2 MB
__device__ __align__(16) __nv_bfloat16 g_B[(size_t)2048 * KP];      // 6.3 MB
__device__ __align__(16) float g_bp[2048];
__device__ __align__(16) float g_leafs_sm[NUM_TREE * NL * ODIM];
__device__ __align__(16) float g_outp[(size_t)NGRP * BATCH * ODIM]; // 8 MB

// ---------------- helpers ----------------
__device__ __forceinline__ uint32_t smem_u32(const void* p) {
    uint32_t a;
    asm("{ .reg .u64 t; cvta.to.shared.u64 t, %1; cvt.u32.u64 %0, t; }" : "=r"(a) : "l"(p));
    return a;
}
__device__ __forceinline__ void cp16(uint32_t dst, const void* src) {
    asm volatile("cp.async.cg.shared.global [%0], [%1], 16;" :: "r"(dst), "l"(src));
}
__device__ __forceinline__ void ldm_x4(uint32_t& r0, uint32_t& r1, uint32_t& r2, uint32_t& r3,
                                       uint32_t addr) {
    asm volatile("ldmatrix.sync.aligned.m8n8.x4.shared.b16 {%0,%1,%2,%3}, [%4];"
                 : "=r"(r0), "=r"(r1), "=r"(r2), "=r"(r3) : "r"(addr));
}
__device__ __forceinline__ void mma_bf16(float& c0, float& c1, float& c2, float& c3,
                                         uint32_t a0, uint32_t a1, uint32_t a2, uint32_t a3,
                                         uint32_t b0, uint32_t b1) {
    asm volatile("mma.sync.aligned.m16n8k16.row.col.f32.bf16.bf16.f32 "
                 "{%0,%1,%2,%3}, {%4,%5,%6,%7}, {%8,%9}, {%0,%1,%2,%3};"
                 : "+f"(c0), "+f"(c1), "+f"(c2), "+f"(c3)
                 : "r"(a0), "r"(a1), "r"(a2), "r"(a3), "r"(b0), "r"(b1));
}

// ---------------- prep kernels ----------------
__global__ void leafs_softmax_kernel(const float* __restrict__ leafs) {
    int i = blockIdx.x * blockDim.x + threadIdx.x;
    if (i >= NUM_TREE * NL) return;
    const float* src = leafs + i * ODIM;
    float m = src[0];
#pragma unroll
    for (int o = 1; o < ODIM; o++) m = fmaxf(m, src[o]);
    float e[ODIM], sum = 0.f;
#pragma unroll
    for (int o = 0; o < ODIM; o++) { e[o] = __expf(src[o] - m); sum += e[o]; }
    float inv = 1.0f / sum;
#pragma unroll
    for (int o = 0; o < ODIM; o++) g_leafs_sm[i * ODIM + o] = e[o] * inv;
}

__global__ void prep_x_kernel(const float* __restrict__ x) {
    int i = blockIdx.x * blockDim.x + threadIdx.x;   // 8192*256 float2s
    int m = i >> 8;
    int k2 = i & 255;
    float2 v = ((const float2*)x)[i];
    __nv_bfloat16 h0 = __float2bfloat16(v.x);
    __nv_bfloat16 h1 = __float2bfloat16(v.y);
    __nv_bfloat162 hh; hh.x = h0; hh.y = h1;
    __nv_bfloat162 ll;
    ll.x = __float2bfloat16(v.x - __bfloat162float(h0));
    ll.y = __float2bfloat16(v.y - __bfloat162float(h1));
    size_t base = (size_t)m * KP + 2 * k2;
    *(__nv_bfloat162*)&g_A[base]        = hh;   // slab 0: xh
    *(__nv_bfloat162*)&g_A[base + 512]  = hh;   // slab 1: xh
    *(__nv_bfloat162*)&g_A[base + 1024] = ll;   // slab 2: xl
}

// B rows padded: row r -> tree r>>5, node r&31 (node 31 = zero); slabs [wh | wl | wh]
__global__ void prep_w_kernel(const float* __restrict__ W, const float* __restrict__ b) {
    int row = blockIdx.y;                               // 0..2047
    int k2  = blockIdx.x * blockDim.x + threadIdx.x;    // 0..767
    int t = row >> 5, ii = row & 31;
    int outcol = 2 * k2;
    int slab = outcol >> 9;
    int kk = outcol & 511;
    __nv_bfloat162 val;
    if (ii < 31) {
        const float2 wv = *(const float2*)&W[((size_t)(t * 31 + ii)) * IN_DIM + kk];
        __nv_bfloat16 h0 = __float2bfloat16(wv.x);
        __nv_bfloat16 h1 = __float2bfloat16(wv.y);
        if (slab == 1) {
            val.x = __float2bfloat16(wv.x - __bfloat162float(h0));
            val.y = __float2bfloat16(wv.y - __bfloat162float(h1));
        } else { val.x = h0; val.y = h1; }
    } else {
        val.x = __float2bfloat16(0.f); val.y = __float2bfloat16(0.f);
    }
    *(__nv_bfloat162*)&g_B[(size_t)row * KP + outcol] = val;
    if (k2 == 0) g_bp[row] = (ii < 31) ? b[t * 31 + ii] : 0.f;
}

// ---------------- fused GEMM (mma.sync) + routing kernel ----------------
__global__ __launch_bounds__(THREADS)
void dndf_mma_kernel() {
    extern __shared__ char smem[];
    const uint32_t sb = smem_u32(smem);

    const int tid = threadIdx.x;
    const int wid = tid >> 5;
    const int lid = tid & 31;
    const int wm = wid & 1;          // 2 m-groups of 64
    const int wn = wid >> 1;         // 4 n-groups of 32
    const int mrow_base = blockIdx.y * BM;
    const int ncol_base = blockIdx.x * BN;

    // cp.async mapping (per thread: 2 A segs + 2 B segs per stage)
    const int r_a  = tid >> 2;        // 0..63 (+64 on second it)
    const int sg_a = tid & 3;

    // ldmatrix lane offsets (bytes within stage A/B regions)
    const int a_row = (lid & 7) + ((lid >> 3) & 1) * 8;
    const int a_k8  = (lid >> 4) * 8;
    const int b_row = (lid & 7) + ((lid >> 4) & 1) * 8;
    const int b_k8  = ((lid >> 3) & 1) * 8;
    uint32_t aoff[4], boff[2];
#pragma unroll
    for (int mi = 0; mi < 4; mi++)
        aoff[mi] = ((wm * 64 + mi * 16 + a_row) * APITCH + a_k8) * 2;
#pragma unroll
    for (int nb = 0; nb < 2; nb++)
        boff[nb] = 10240u + ((wn * 32 + nb * 16 + b_row) * APITCH + b_k8) * 2;

    float acc[4][4][4];
#pragma unroll
    for (int i = 0; i < 4; i++)
#pragma unroll
        for (int j = 0; j < 4; j++)
#pragma unroll
            for (int r = 0; r < 4; r++) acc[i][j][r] = 0.f;

    // ---- prefetch stages 0..NSTAGE-2 ----
#pragma unroll
    for (int s = 0; s < NSTAGE - 1; s++) {
        const uint32_t st = sb + s * STAGE_BYTES;
        const int kbase = s * BK;
#pragma unroll
        for (int it = 0; it < 2; it++) {
            int r = r_a + it * 64;
            cp16(st + (uint32_t)(r * APITCH + sg_a * 8) * 2,
                 (const char*)g_A + ((size_t)(mrow_base + r) * KP + kbase + sg_a * 8) * 2);
        }
#pragma unroll
        for (int it = 0; it < 2; it++) {
            int r = r_a + it * 64;
            cp16(st + 10240u + (uint32_t)(r * APITCH + sg_a * 8) * 2,
                 (const char*)g_B + ((size_t)(ncol_base + r) * KP + kbase + sg_a * 8) * 2);
        }
        asm volatile("cp.async.commit_group;" ::: "memory");
    }

    // ---- mainloop: per chunk, all 12 ldmatrix up front, then 32 MMAs ----
#pragma unroll 1
    for (int c = 0; c < NKCH; c++) {
        asm volatile("cp.async.wait_group %0;" :: "n"(NSTAGE - 2) : "memory");
        __syncthreads();

        const int cn = c + NSTAGE - 1;
        if (cn < NKCH) {
            const uint32_t st = sb + (cn & 3) * STAGE_BYTES;
            const int kbase = cn * BK;
#pragma unroll
            for (int it = 0; it < 2; it++) {
                int r = r_a + it * 64;
                cp16(st + (uint32_t)(r * APITCH + sg_a * 8) * 2,
                     (const char*)g_A + ((size_t)(mrow_base + r) * KP + kbase + sg_a * 8) * 2);
            }
#pragma unroll
            for (int it = 0; it < 2; it++) {
                int r = r_a + it * 64;
                cp16(st + 10240u + (uint32_t)(r * APITCH + sg_a * 8) * 2,
                     (const char*)g_B + ((size_t)(ncol_base + r) * KP + kbase + sg_a * 8) * 2);
            }
        }
        asm volatile("cp.async.commit_group;" ::: "memory");

        const uint32_t st = sb + (c & 3) * STAGE_BYTES;
        uint32_t a[2][4][4], b[2][2][4];
#pragma unroll
        for (int kk = 0; kk < 2; kk++) {
#pragma unroll
            for (int mi = 0; mi < 4; mi++)
                ldm_x4(a[kk][mi][0], a[kk][mi][1], a[kk][mi][2], a[kk][mi][3],
                       st + aoff[mi] + kk * 32);
#pragma unroll
            for (int nb = 0; nb < 2; nb++)
                ldm_x4(b[kk][nb][0], b[kk][nb][1], b[kk][nb][2], b[kk][nb][3],
                       st + boff[nb] + kk * 32);
        }
#pragma unroll
        for (int kk = 0; kk < 2; kk++) {
#pragma unroll
            for (int mi = 0; mi < 4; mi++) {
#pragma unroll
                for (int nb = 0; nb < 2; nb++) {
                    mma_bf16(acc[mi][nb * 2][0],     acc[mi][nb * 2][1],
                             acc[mi][nb * 2][2],     acc[mi][nb * 2][3],
                             a[kk][mi][0], a[kk][mi][1], a[kk][mi][2], a[kk][mi][3],
                             b[kk][nb][0], b[kk][nb][1]);
                    mma_bf16(acc[mi][nb * 2 + 1][0], acc[mi][nb * 2 + 1][1],
                             acc[mi][nb * 2 + 1][2], acc[mi][nb * 2 + 1][3],
                             a[kk][mi][0], a[kk][mi][1], a[kk][mi][2], a[kk][mi][3],
                             b[kk][nb][2], b[kk][nb][3]);
                }
            }
        }
    }

    asm volatile("cp.async.wait_group 0;" ::: "memory");
    __syncthreads();   // mainloop done; smem free for reuse

    // ---- stage bias + leaf tables ----
    float* p_s    = (float*)(smem + UOFF_P);
    float* lf_s   = (float*)(smem + UOFF_LF);
    float* bias_s = (float*)(smem + UOFF_BIAS);
    if (tid < 128) bias_s[tid] = g_bp[ncol_base + tid];
    {
        const float4* src = (const float4*)&g_leafs_sm[(size_t)(blockIdx.x * 4) * NL * ODIM];
        float4* dst = (float4*)lf_s;
#pragma unroll
        for (int i = tid; i < 4 * NL * ODIM / 4; i += THREADS) dst[i] = src[i];
    }
    __syncthreads();

    // ---- sigmoid(acc + bias) -> p_s, tree-interleaved: p_s[row][node*4 + tree] ----
    const int lr = lid >> 2;          // lane row 0..7
    const int lc = (lid & 3) * 2;     // lane col 0,2,4,6
#pragma unroll
    for (int mi = 0; mi < 4; mi++) {
#pragma unroll
        for (int ni = 0; ni < 4; ni++) {
            const int colb = wn * 32 + ni * 8 + lc;
            const int rowb = wm * 64 + mi * 16 + lr;
#pragma unroll
            for (int r = 0; r < 4; r++) {
                const int row = rowb + (r >> 1) * 8;
                const int col = colb + (r & 1);           // 0..127 = tree*32 + node
                const int icol = (col & 31) * 4 + (col >> 5);
                const float v = acc[mi][ni][r] + bias_s[col];
                p_s[row * P_PITCH + icol] = 1.0f / (1.0f + __expf(-v));
            }
        }
    }
    __syncthreads();

    // ---- routing + leaf contraction (register-lean) ----
    // warp wid owns rows [wid*16, wid*16+16); lane l = (row_quad = l>>2, tree = l&3).
    {
        const int t = lid & 3;
        const float4* ls4 = (const float4*)&lf_s[(t * NL) * ODIM];
#pragma unroll 1
        for (int j = 0; j < 2; j++) {
            const int row = wid * 16 + (lid >> 2) + j * 8;
            const float* P = &p_s[row * P_PITCH + t];   // node i at P[i*4]

            float bb[4], cc[8], dd[16];
            {
                float p0 = P[0];
                float p1 = P[4], p2 = P[8];
                float s01 = p0 * p1;
                float s02 = p2 - p0 * p2;      // (1-p0)*p2
                bb[0] = s01;         bb[1] = p0 - s01;
                bb[2] = s02;         bb[3] = (1.0f - p0) - s02;
            }
#pragma unroll
            for (int q = 0; q < 4; q++) {
                float pv = P[(3 + q) * 4];
                float s = bb[q] * pv;
                cc[2 * q] = s; cc[2 * q + 1] = bb[q] - s;
            }
#pragma unroll
            for (int q = 0; q < 8; q++) {
                float pv = P[(7 + q) * 4];
                float s = cc[q] * pv;
                dd[2 * q] = s; dd[2 * q + 1] = cc[q] - s;
            }

            float oacc[ODIM];
#pragma unroll
            for (int o = 0; o < ODIM; o++) oacc[o] = 0.f;

#pragma unroll
            for (int q = 0; q < 16; q++) {
                float pv = P[(15 + q) * 4];
                float r0 = dd[q] * pv;
                float r1 = dd[q] - r0;
                {
                    float4 v0 = ls4[(2 * q) * 4 + 0], v1 = ls4[(2 * q) * 4 + 1];
                    float4 v2 = ls4[(2 * q) * 4 + 2], v3 = ls4[(2 * q) * 4 + 3];
                    oacc[0]  = fmaf(r0, v0.x, oacc[0]);  oacc[1]  = fmaf(r0, v0.y, oacc[1]);
                    oacc[2]  = fmaf(r0, v0.z, oacc[2]);  oacc[3]  = fmaf(r0, v0.w, oacc[3]);
                    oacc[4]  = fmaf(r0, v1.x, oacc[4]);  oacc[5]  = fmaf(r0, v1.y, oacc[5]);
                    oacc[6]  = fmaf(r0, v1.z, oacc[6]);  oacc[7]  = fmaf(r0, v1.w, oacc[7]);
                    oacc[8]  = fmaf(r0, v2.x, oacc[8]);  oacc[9]  = fmaf(r0, v2.y, oacc[9]);
                    oacc[10] = fmaf(r0, v2.z, oacc[10]); oacc[11] = fmaf(r0, v2.w, oacc[11]);
                    oacc[12] = fmaf(r0, v3.x, oacc[12]); oacc[13] = fmaf(r0, v3.y, oacc[13]);
                    oacc[14] = fmaf(r0, v3.z, oacc[14]); oacc[15] = fmaf(r0, v3.w, oacc[15]);
                }
                {
                    float4 v0 = ls4[(2 * q + 1) * 4 + 0], v1 = ls4[(2 * q + 1) * 4 + 1];
                    float4 v2 = ls4[(2 * q + 1) * 4 + 2], v3 = ls4[(2 * q + 1) * 4 + 3];
                    oacc[0]  = fmaf(r1, v0.x, oacc[0]);  oacc[1]  = fmaf(r1, v0.y, oacc[1]);
                    oacc[2]  = fmaf(r1, v0.z, oacc[2]);  oacc[3]  = fmaf(r1, v0.w, oacc[3]);
                    oacc[4]  = fmaf(r1, v1.x, oacc[4]);  oacc[5]  = fmaf(r1, v1.y, oacc[5]);
                    oacc[6]  = fmaf(r1, v1.z, oacc[6]);  oacc[7]  = fmaf(r1, v1.w, oacc[7]);
                    oacc[8]  = fmaf(r1, v2.x, oacc[8]);  oacc[9]  = fmaf(r1, v2.y, oacc[9]);
                    oacc[10] = fmaf(r1, v2.z, oacc[10]); oacc[11] = fmaf(r1, v2.w, oacc[11]);
                    oacc[12] = fmaf(r1, v3.x, oacc[12]); oacc[13] = fmaf(r1, v3.y, oacc[13]);
                    oacc[14] = fmaf(r1, v3.z, oacc[14]); oacc[15] = fmaf(r1, v3.w, oacc[15]);
                }
            }

            // sum the 4 trees of this row (lane-quad butterfly)
#pragma unroll
            for (int o = 0; o < ODIM; o++) {
                oacc[o] += __shfl_xor_sync(0xffffffffu, oacc[o], 1);
                oacc[o] += __shfl_xor_sync(0xffffffffu, oacc[o], 2);
            }
            // all 4 lanes hold the row sum; lane t writes float4 quarter t
            float4 v = make_float4(oacc[t * 4 + 0], oacc[t * 4 + 1],
                                   oacc[t * 4 + 2], oacc[t * 4 + 3]);
            *(float4*)&g_outp[((size_t)blockIdx.x * BATCH + mrow_base + row) * ODIM + t * 4] = v;
        }
    }
}

// ---------------- final reduce over the 16 N-groups ----------------
__global__ void reduce_kernel(float* __restrict__ out) {
    int i = blockIdx.x * blockDim.x + threadIdx.x;   // 32768 float4s
    float4 acc = make_float4(0.f, 0.f, 0.f, 0.f);
#pragma unroll
    for (int g = 0; g < NGRP; g++) {
        float4 v = ((const float4*)g_outp)[(size_t)g * (BATCH * 4) + i];
        acc.x += v.x; acc.y += v.y; acc.z += v.z; acc.w += v.w;
    }
    const float s = 1.0f / NUM_TREE;
    ((float4*)out)[i] = make_float4(acc.x * s, acc.y * s, acc.z * s, acc.w * s);
}

// ---------------- launch ----------------
extern "C" void kernel_launch(void* const* d_in, const int* in_sizes, int n_in,
                              void* d_out, int out_size) {
    const float* x     = (const float*)d_in[0];   // [8192, 512]
    const float* W     = (const float*)d_in[1];   // [1984, 512]
    const float* b     = (const float*)d_in[2];   // [1984]
    const float* leafs = (const float*)d_in[3];   // [64, 32, 16]
    float* out = (float*)d_out;                   // [8192, 16]

    leafs_softmax_kernel<<<(NUM_TREE * NL + 255) / 256, 256>>>(leafs);
    prep_x_kernel<<<(BATCH * 256) / 256, 256>>>(x);
    prep_w_kernel<<<dim3(3, 2048), 256>>>(W, b);

    cudaFuncSetAttribute(dndf_mma_kernel,
                         cudaFuncAttributeMaxDynamicSharedMemorySize, SMEM_TOTAL);
    dndf_mma_kernel<<<dim3(NGRP, BATCH / BM), THREADS, SMEM_TOTAL>>>();

    reduce_kernel<<<(BATCH * 4) / 256, 256>>>(out);
}

// round 7
// speedup vs baseline: 1.0755x; 1.0755x over previous
#include <cuda_runtime.h>
#include <cuda_bf16.h>
#include <cstdint>

// ---------------- problem constants ----------------
#define BATCH    8192
#define IN_DIM   512
#define NUM_TREE 64
#define NI       31
#define NL       32
#define ODIM     16

// ---------------- GEMM tiling ----------------
#define KP       1536        // packed K: [xh | xh | xl] vs [wh | wl | wh]
#define BM       128
#define BN       128         // 4 trees * 32 padded cols
#define BK       32
#define NKCH     (KP / BK)   // 48
#define NSTAGE   4
#define THREADS  512         // 16 warps, 4x4 warp grid, 32x32 tiles
#define APITCH   40          // bf16 elems per smem row (32 + 8 pad -> 80B stride)
#define NGRP     16          // N groups (16 * 128 = 2048 padded nodes)

#define STAGE_BYTES   20480u                 // A(10240) + B(10240)
#define SMEM_TOTAL    (STAGE_BYTES * NSTAGE) // 81920
// union region (reused after mainloop):
#define P_PITCH   133
#define UOFF_P    0u                         // float[128*133] = 68096 B
#define UOFF_LF   68096u                     // float[4*32*16] = 8192 B
#define UOFF_BIAS 76288u                     // float[128]     = 512 B

// ---------------- device scratch ----------------
__device__ __align__(16) __nv_bfloat16 g_A[(size_t)BATCH * KP];     // 25.2 MB
__device__ __align__(16) __nv_bfloat16 g_B[(size_t)2048 * KP];      // 6.3 MB
__device__ __align__(16) float g_bp[2048];
__device__ __align__(16) float g_leafs_sm[NUM_TREE * NL * ODIM];
__device__ __align__(16) float g_outp[(size_t)NGRP * BATCH * ODIM]; // 8 MB

// ---------------- helpers ----------------
__device__ __forceinline__ uint32_t smem_u32(const void* p) {
    uint32_t a;
    asm("{ .reg .u64 t; cvta.to.shared.u64 t, %1; cvt.u32.u64 %0, t; }" : "=r"(a) : "l"(p));
    return a;
}
__device__ __forceinline__ void cp16(uint32_t dst, const void* src) {
    asm volatile("cp.async.cg.shared.global [%0], [%1], 16;" :: "r"(dst), "l"(src));
}
__device__ __forceinline__ void ldm_x4(uint32_t& r0, uint32_t& r1, uint32_t& r2, uint32_t& r3,
                                       uint32_t addr) {
    asm volatile("ldmatrix.sync.aligned.m8n8.x4.shared.b16 {%0,%1,%2,%3}, [%4];"
                 : "=r"(r0), "=r"(r1), "=r"(r2), "=r"(r3) : "r"(addr));
}
__device__ __forceinline__ void mma_bf16(float& c0, float& c1, float& c2, float& c3,
                                         uint32_t a0, uint32_t a1, uint32_t a2, uint32_t a3,
                                         uint32_t b0, uint32_t b1) {
    asm volatile("mma.sync.aligned.m16n8k16.row.col.f32.bf16.bf16.f32 "
                 "{%0,%1,%2,%3}, {%4,%5,%6,%7}, {%8,%9}, {%0,%1,%2,%3};"
                 : "+f"(c0), "+f"(c1), "+f"(c2), "+f"(c3)
                 : "r"(a0), "r"(a1), "r"(a2), "r"(a3), "r"(b0), "r"(b1));
}

// ---------------- prep kernels ----------------
__global__ void leafs_softmax_kernel(const float* __restrict__ leafs) {
    int i = blockIdx.x * blockDim.x + threadIdx.x;
    if (i >= NUM_TREE * NL) return;
    const float* src = leafs + i * ODIM;
    float m = src[0];
#pragma unroll
    for (int o = 1; o < ODIM; o++) m = fmaxf(m, src[o]);
    float e[ODIM], sum = 0.f;
#pragma unroll
    for (int o = 0; o < ODIM; o++) { e[o] = __expf(src[o] - m); sum += e[o]; }
    float inv = 1.0f / sum;
#pragma unroll
    for (int o = 0; o < ODIM; o++) g_leafs_sm[i * ODIM + o] = e[o] * inv;
}

__global__ void prep_x_kernel(const float* __restrict__ x) {
    int i = blockIdx.x * blockDim.x + threadIdx.x;   // 8192*256 float2s
    int m = i >> 8;
    int k2 = i & 255;
    float2 v = ((const float2*)x)[i];
    __nv_bfloat16 h0 = __float2bfloat16(v.x);
    __nv_bfloat16 h1 = __float2bfloat16(v.y);
    __nv_bfloat162 hh; hh.x = h0; hh.y = h1;
    __nv_bfloat162 ll;
    ll.x = __float2bfloat16(v.x - __bfloat162float(h0));
    ll.y = __float2bfloat16(v.y - __bfloat162float(h1));
    size_t base = (size_t)m * KP + 2 * k2;
    *(__nv_bfloat162*)&g_A[base]        = hh;   // slab 0: xh
    *(__nv_bfloat162*)&g_A[base + 512]  = hh;   // slab 1: xh
    *(__nv_bfloat162*)&g_A[base + 1024] = ll;   // slab 2: xl
}

// B rows padded: row r -> tree r>>5, node r&31 (node 31 = zero); slabs [wh | wl | wh]
__global__ void prep_w_kernel(const float* __restrict__ W, const float* __restrict__ b) {
    int row = blockIdx.y;                               // 0..2047
    int k2  = blockIdx.x * blockDim.x + threadIdx.x;    // 0..767
    int t = row >> 5, ii = row & 31;
    int outcol = 2 * k2;
    int slab = outcol >> 9;
    int kk = outcol & 511;
    __nv_bfloat162 val;
    if (ii < 31) {
        const float2 wv = *(const float2*)&W[((size_t)(t * 31 + ii)) * IN_DIM + kk];
        __nv_bfloat16 h0 = __float2bfloat16(wv.x);
        __nv_bfloat16 h1 = __float2bfloat16(wv.y);
        if (slab == 1) {
            val.x = __float2bfloat16(wv.x - __bfloat162float(h0));
            val.y = __float2bfloat16(wv.y - __bfloat162float(h1));
        } else { val.x = h0; val.y = h1; }
    } else {
        val.x = __float2bfloat16(0.f); val.y = __float2bfloat16(0.f);
    }
    *(__nv_bfloat162*)&g_B[(size_t)row * KP + outcol] = val;
    if (k2 == 0) g_bp[row] = (ii < 31) ? b[t * 31 + ii] : 0.f;
}

// ---------------- fused GEMM (mma.sync) + routing kernel ----------------
__global__ __launch_bounds__(THREADS, 1)
void dndf_mma_kernel() {
    extern __shared__ char smem[];
    const uint32_t sb = smem_u32(smem);

    const int tid = threadIdx.x;
    const int wid = tid >> 5;
    const int lid = tid & 31;
    const int wm = wid & 3;          // 4 m-groups of 32 rows
    const int wn = wid >> 2;         // 4 n-groups of 32 cols
    const int mrow_base = blockIdx.y * BM;
    const int ncol_base = blockIdx.x * BN;

    // cp.async mapping: 1 A seg + 1 B seg per thread per stage
    const int r_a  = tid >> 2;        // 0..127
    const int sg_a = tid & 3;

    // ldmatrix lane offsets
    const int a_row = (lid & 7) + ((lid >> 3) & 1) * 8;
    const int a_k8  = (lid >> 4) * 8;
    const int b_row = (lid & 7) + ((lid >> 4) & 1) * 8;
    const int b_k8  = ((lid >> 3) & 1) * 8;
    uint32_t aoff[2], boff[2];
#pragma unroll
    for (int mi = 0; mi < 2; mi++)
        aoff[mi] = ((wm * 32 + mi * 16 + a_row) * APITCH + a_k8) * 2;
#pragma unroll
    for (int nb = 0; nb < 2; nb++)
        boff[nb] = 10240u + ((wn * 32 + nb * 16 + b_row) * APITCH + b_k8) * 2;

    float acc[2][4][4];
#pragma unroll
    for (int i = 0; i < 2; i++)
#pragma unroll
        for (int j = 0; j < 4; j++)
#pragma unroll
            for (int r = 0; r < 4; r++) acc[i][j][r] = 0.f;

    // ---- prefetch stages 0..NSTAGE-2 ----
#pragma unroll
    for (int s = 0; s < NSTAGE - 1; s++) {
        const uint32_t st = sb + s * STAGE_BYTES;
        const int kbase = s * BK;
        cp16(st + (uint32_t)(r_a * APITCH + sg_a * 8) * 2,
             (const char*)g_A + ((size_t)(mrow_base + r_a) * KP + kbase + sg_a * 8) * 2);
        cp16(st + 10240u + (uint32_t)(r_a * APITCH + sg_a * 8) * 2,
             (const char*)g_B + ((size_t)(ncol_base + r_a) * KP + kbase + sg_a * 8) * 2);
        asm volatile("cp.async.commit_group;" ::: "memory");
    }

    // ---- mainloop ----
#pragma unroll 1
    for (int c = 0; c < NKCH; c++) {
        asm volatile("cp.async.wait_group %0;" :: "n"(NSTAGE - 2) : "memory");
        __syncthreads();

        const int cn = c + NSTAGE - 1;
        if (cn < NKCH) {
            const uint32_t st = sb + (cn & 3) * STAGE_BYTES;
            const int kbase = cn * BK;
            cp16(st + (uint32_t)(r_a * APITCH + sg_a * 8) * 2,
                 (const char*)g_A + ((size_t)(mrow_base + r_a) * KP + kbase + sg_a * 8) * 2);
            cp16(st + 10240u + (uint32_t)(r_a * APITCH + sg_a * 8) * 2,
                 (const char*)g_B + ((size_t)(ncol_base + r_a) * KP + kbase + sg_a * 8) * 2);
        }
        asm volatile("cp.async.commit_group;" ::: "memory");

        const uint32_t st = sb + (c & 3) * STAGE_BYTES;
#pragma unroll
        for (int kk = 0; kk < 2; kk++) {   // two k16 steps per BK=32
            uint32_t a[2][4], b[2][4];
#pragma unroll
            for (int mi = 0; mi < 2; mi++)
                ldm_x4(a[mi][0], a[mi][1], a[mi][2], a[mi][3], st + aoff[mi] + kk * 32);
#pragma unroll
            for (int nb = 0; nb < 2; nb++)
                ldm_x4(b[nb][0], b[nb][1], b[nb][2], b[nb][3], st + boff[nb] + kk * 32);
#pragma unroll
            for (int mi = 0; mi < 2; mi++) {
#pragma unroll
                for (int nb = 0; nb < 2; nb++) {
                    mma_bf16(acc[mi][nb * 2][0],     acc[mi][nb * 2][1],
                             acc[mi][nb * 2][2],     acc[mi][nb * 2][3],
                             a[mi][0], a[mi][1], a[mi][2], a[mi][3],
                             b[nb][0], b[nb][1]);
                    mma_bf16(acc[mi][nb * 2 + 1][0], acc[mi][nb * 2 + 1][1],
                             acc[mi][nb * 2 + 1][2], acc[mi][nb * 2 + 1][3],
                             a[mi][0], a[mi][1], a[mi][2], a[mi][3],
                             b[nb][2], b[nb][3]);
                }
            }
        }
    }

    asm volatile("cp.async.wait_group 0;" ::: "memory");
    __syncthreads();   // mainloop done; smem free for reuse

    // ---- stage bias + leaf tables ----
    float* p_s    = (float*)(smem + UOFF_P);
    float* lf_s   = (float*)(smem + UOFF_LF);
    float* bias_s = (float*)(smem + UOFF_BIAS);
    if (tid < 128) bias_s[tid] = g_bp[ncol_base + tid];
    {
        const float4* src = (const float4*)&g_leafs_sm[(size_t)(blockIdx.x * 4) * NL * ODIM];
        float4* dst = (float4*)lf_s;
        if (tid < 4 * NL * ODIM / 4) dst[tid] = src[tid];
    }
    __syncthreads();

    // ---- sigmoid(acc + bias) -> p_s, tree-interleaved: p_s[row][node*4 + tree] ----
    const int lr = lid >> 2;          // lane row 0..7
    const int lc = (lid & 3) * 2;     // lane col 0,2,4,6
#pragma unroll
    for (int mi = 0; mi < 2; mi++) {
#pragma unroll
        for (int ni = 0; ni < 4; ni++) {
            const int colb = wn * 32 + ni * 8 + lc;
            const int rowb = wm * 32 + mi * 16 + lr;
#pragma unroll
            for (int r = 0; r < 4; r++) {
                const int row = rowb + (r >> 1) * 8;
                const int col = colb + (r & 1);           // 0..127 = tree*32 + node
                const int icol = (col & 31) * 4 + (col >> 5);
                const float v = acc[mi][ni][r] + bias_s[col];
                p_s[row * P_PITCH + icol] = 1.0f / (1.0f + __expf(-v));
            }
        }
    }
    __syncthreads();

    // ---- routing + leaf contraction: 512 tasks, one per thread ----
    // warp wid owns rows [wid*8, wid*8+8); lane l = (row = wid*8 + (l>>2), tree = l&3).
    {
        const int t = lid & 3;
        const int row = wid * 8 + (lid >> 2);
        const float4* ls4 = (const float4*)&lf_s[(t * NL) * ODIM];
        const float* P = &p_s[row * P_PITCH + t];   // node i at P[i*4]

        float bb[4], cc[8], dd[16];
        {
            float p0 = P[0];
            float p1 = P[4], p2 = P[8];
            float s01 = p0 * p1;
            float s02 = p2 - p0 * p2;      // (1-p0)*p2
            bb[0] = s01;         bb[1] = p0 - s01;
            bb[2] = s02;         bb[3] = (1.0f - p0) - s02;
        }
#pragma unroll
        for (int q = 0; q < 4; q++) {
            float pv = P[(3 + q) * 4];
            float s = bb[q] * pv;
            cc[2 * q] = s; cc[2 * q + 1] = bb[q] - s;
        }
#pragma unroll
        for (int q = 0; q < 8; q++) {
            float pv = P[(7 + q) * 4];
            float s = cc[q] * pv;
            dd[2 * q] = s; dd[2 * q + 1] = cc[q] - s;
        }

        float oacc[ODIM];
#pragma unroll
        for (int o = 0; o < ODIM; o++) oacc[o] = 0.f;

#pragma unroll
        for (int q = 0; q < 16; q++) {
            float pv = P[(15 + q) * 4];
            float r0 = dd[q] * pv;
            float r1 = dd[q] - r0;
            {
                float4 v0 = ls4[(2 * q) * 4 + 0], v1 = ls4[(2 * q) * 4 + 1];
                float4 v2 = ls4[(2 * q) * 4 + 2], v3 = ls4[(2 * q) * 4 + 3];
                oacc[0]  = fmaf(r0, v0.x, oacc[0]);  oacc[1]  = fmaf(r0, v0.y, oacc[1]);
                oacc[2]  = fmaf(r0, v0.z, oacc[2]);  oacc[3]  = fmaf(r0, v0.w, oacc[3]);
                oacc[4]  = fmaf(r0, v1.x, oacc[4]);  oacc[5]  = fmaf(r0, v1.y, oacc[5]);
                oacc[6]  = fmaf(r0, v1.z, oacc[6]);  oacc[7]  = fmaf(r0, v1.w, oacc[7]);
                oacc[8]  = fmaf(r0, v2.x, oacc[8]);  oacc[9]  = fmaf(r0, v2.y, oacc[9]);
                oacc[10] = fmaf(r0, v2.z, oacc[10]); oacc[11] = fmaf(r0, v2.w, oacc[11]);
                oacc[12] = fmaf(r0, v3.x, oacc[12]); oacc[13] = fmaf(r0, v3.y, oacc[13]);
                oacc[14] = fmaf(r0, v3.z, oacc[14]); oacc[15] = fmaf(r0, v3.w, oacc[15]);
            }
            {
                float4 v0 = ls4[(2 * q + 1) * 4 + 0], v1 = ls4[(2 * q + 1) * 4 + 1];
                float4 v2 = ls4[(2 * q + 1) * 4 + 2], v3 = ls4[(2 * q + 1) * 4 + 3];
                oacc[0]  = fmaf(r1, v0.x, oacc[0]);  oacc[1]  = fmaf(r1, v0.y, oacc[1]);
                oacc[2]  = fmaf(r1, v0.z, oacc[2]);  oacc[3]  = fmaf(r1, v0.w, oacc[3]);
                oacc[4]  = fmaf(r1, v1.x, oacc[4]);  oacc[5]  = fmaf(r1, v1.y, oacc[5]);
                oacc[6]  = fmaf(r1, v1.z, oacc[6]);  oacc[7]  = fmaf(r1, v1.w, oacc[7]);
                oacc[8]  = fmaf(r1, v2.x, oacc[8]);  oacc[9]  = fmaf(r1, v2.y, oacc[9]);
                oacc[10] = fmaf(r1, v2.z, oacc[10]); oacc[11] = fmaf(r1, v2.w, oacc[11]);
                oacc[12] = fmaf(r1, v3.x, oacc[12]); oacc[13] = fmaf(r1, v3.y, oacc[13]);
                oacc[14] = fmaf(r1, v3.z, oacc[14]); oacc[15] = fmaf(r1, v3.w, oacc[15]);
            }
        }

        // sum the 4 trees of this row (lane-quad butterfly)
#pragma unroll
        for (int o = 0; o < ODIM; o++) {
            oacc[o] += __shfl_xor_sync(0xffffffffu, oacc[o], 1);
            oacc[o] += __shfl_xor_sync(0xffffffffu, oacc[o], 2);
        }
        // all 4 lanes hold the row sum; lane t writes float4 quarter t
        float4 v = make_float4(oacc[t * 4 + 0], oacc[t * 4 + 1],
                               oacc[t * 4 + 2], oacc[t * 4 + 3]);
        *(float4*)&g_outp[((size_t)blockIdx.x * BATCH + mrow_base + row) * ODIM + t * 4] = v;
    }
}

// ---------------- final reduce over the 16 N-groups ----------------
__global__ void reduce_kernel(float* __restrict__ out) {
    int i = blockIdx.x * blockDim.x + threadIdx.x;   // 32768 float4s
    float4 acc = make_float4(0.f, 0.f, 0.f, 0.f);
#pragma unroll
    for (int g = 0; g < NGRP; g++) {
        float4 v = ((const float4*)g_outp)[(size_t)g * (BATCH * 4) + i];
        acc.x += v.x; acc.y += v.y; acc.z += v.z; acc.w += v.w;
    }
    const float s = 1.0f / NUM_TREE;
    ((float4*)out)[i] = make_float4(acc.x * s, acc.y * s, acc.z * s, acc.w * s);
}

// ---------------- launch ----------------
extern "C" void kernel_launch(void* const* d_in, const int* in_sizes, int n_in,
                              void* d_out, int out_size) {
    const float* x     = (const float*)d_in[0];   // [8192, 512]
    const float* W     = (const float*)d_in[1];   // [1984, 512]
    const float* b     = (const float*)d_in[2];   // [1984]
    const float* leafs = (const float*)d_in[3];   // [64, 32, 16]
    float* out = (float*)d_out;                   // [8192, 16]

    leafs_softmax_kernel<<<(NUM_TREE * NL + 255) / 256, 256>>>(leafs);
    prep_x_kernel<<<(BATCH * 256) / 256, 256>>>(x);
    prep_w_kernel<<<dim3(3, 2048), 256>>>(W, b);

    cudaFuncSetAttribute(dndf_mma_kernel,
                         cudaFuncAttributeMaxDynamicSharedMemorySize, SMEM_TOTAL);
    dndf_mma_kernel<<<dim3(NGRP, BATCH / BM), THREADS, SMEM_TOTAL>>>();

    reduce_kernel<<<(BATCH * 4) / 256, 256>>>(out);
}

// round 8
// speedup vs baseline: 1.3342x; 1.2405x over previous
#include <cuda_runtime.h>
#include <cstdint>

// ---------------- problem constants ----------------
#define BATCH    8192
#define IN_DIM   512
#define NUM_TREE 64
#define NI       31
#define NL       32
#define ODIM     16

// ---------------- GEMM tiling (tf32 m16n8k8, fragment-major) ----------------
#define BM       128
#define BN       128         // 4 trees * 32 padded cols
#define BK       32          // 4 k8 steps per chunk
#define NKCH     (IN_DIM / BK)   // 16
#define NSTAGE   3
#define THREADS  512         // 16 warps: 4 m-groups x 4 n-groups, 32x32 warp tiles
#define NGRP     16          // N groups (16 * 128 = 2048 padded nodes)

// stage: A = 8 mtiles * 4 k8 * 512B = 16384; B = 16 ntiles * 4 k8 * 256B = 16384
#define A_STAGE_BYTES 16384u
#define STAGE_BYTES   32768u
#define SMEM_TOTAL    (STAGE_BYTES * NSTAGE)   // 98304
// union region (reused after mainloop):
#define P_PITCH   133
#define UOFF_P    0u                           // float[128*133] = 68096 B
#define UOFF_LF   68096u                       // float[4*32*16] = 8192 B
#define UOFF_BIAS 76288u                       // float[128]     = 512 B

// ---------------- device scratch ----------------
// A fragments: [512 mtiles][64 k8][32 lanes][4 regs] u32  = 16.8 MB
__device__ __align__(16) uint32_t g_A[(size_t)(BATCH / 16) * 64 * 32 * 4];
// B fragments: [256 ntiles][64 k8][32 lanes][2 regs] u32  = 4 MB
__device__ __align__(16) uint32_t g_B[(size_t)(2048 / 8) * 64 * 32 * 2];
__device__ __align__(16) float g_bp[2048];
__device__ __align__(16) float g_leafs_sm[NUM_TREE * NL * ODIM];
__device__ __align__(16) float g_outp[(size_t)NGRP * BATCH * ODIM];  // 8 MB

// ---------------- helpers ----------------
__device__ __forceinline__ uint32_t smem_u32(const void* p) {
    uint32_t a;
    asm("{ .reg .u64 t; cvta.to.shared.u64 t, %1; cvt.u32.u64 %0, t; }" : "=r"(a) : "l"(p));
    return a;
}
__device__ __forceinline__ void cp16(uint32_t dst, const void* src) {
    asm volatile("cp.async.cg.shared.global [%0], [%1], 16;" :: "r"(dst), "l"(src));
}
__device__ __forceinline__ void lds128(uint32_t& r0, uint32_t& r1, uint32_t& r2, uint32_t& r3,
                                       uint32_t addr) {
    asm volatile("ld.shared.v4.b32 {%0,%1,%2,%3}, [%4];"
                 : "=r"(r0), "=r"(r1), "=r"(r2), "=r"(r3) : "r"(addr));
}
__device__ __forceinline__ void lds64(uint32_t& r0, uint32_t& r1, uint32_t addr) {
    asm volatile("ld.shared.v2.b32 {%0,%1}, [%2];" : "=r"(r0), "=r"(r1) : "r"(addr));
}
__device__ __forceinline__ void mma_tf32(float& c0, float& c1, float& c2, float& c3,
                                         uint32_t a0, uint32_t a1, uint32_t a2, uint32_t a3,
                                         uint32_t b0, uint32_t b1) {
    asm volatile("mma.sync.aligned.m16n8k8.row.col.f32.tf32.tf32.f32 "
                 "{%0,%1,%2,%3}, {%4,%5,%6,%7}, {%8,%9}, {%0,%1,%2,%3};"
                 : "+f"(c0), "+f"(c1), "+f"(c2), "+f"(c3)
                 : "r"(a0), "r"(a1), "r"(a2), "r"(a3), "r"(b0), "r"(b1));
}
__device__ __forceinline__ uint32_t f2tf32(float v) {
    uint32_t t;
    asm("cvt.rna.tf32.f32 %0, %1;" : "=r"(t) : "f"(v));
    return t;
}

// ---------------- prep kernels ----------------
__global__ void leafs_softmax_kernel(const float* __restrict__ leafs) {
    int i = blockIdx.x * blockDim.x + threadIdx.x;
    if (i >= NUM_TREE * NL) return;
    const float* src = leafs + i * ODIM;
    float m = src[0];
#pragma unroll
    for (int o = 1; o < ODIM; o++) m = fmaxf(m, src[o]);
    float e[ODIM], sum = 0.f;
#pragma unroll
    for (int o = 0; o < ODIM; o++) { e[o] = __expf(src[o] - m); sum += e[o]; }
    float inv = 1.0f / sum;
#pragma unroll
    for (int o = 0; o < ODIM; o++) g_leafs_sm[i * ODIM + o] = e[o] * inv;
}

// x -> tf32 A fragments: [mtile][k8][lane][reg]
__global__ void prep_x_kernel(const float* __restrict__ x) {
    int i = blockIdx.x * blockDim.x + threadIdx.x;   // 0 .. 8192*512-1
    int m = i >> 9, k = i & 511;
    uint32_t tv = f2tf32(x[i]);
    int mtile = m >> 4, row = m & 15, k8 = k >> 3, col = k & 7;
    int r = row & 7, hi = row >> 3;
    int reg = ((col >> 2) << 1) | hi;    // a0:[r<8,c<4] a1:[r>=8,c<4] a2:[r<8,c>=4] a3
    int lane = r * 4 + (col & 3);
    g_A[(((size_t)mtile * 64 + k8) * 32 + lane) * 4 + reg] = tv;
}

// W (tree-permuted, node31 zero) -> tf32 B fragments: [ntile][k8][lane][reg]
__global__ void prep_w_kernel(const float* __restrict__ W, const float* __restrict__ b) {
    int i = blockIdx.x * blockDim.x + threadIdx.x;   // 0 .. 2048*512-1
    int n = i >> 9, k = i & 511;
    int t = n >> 5, ii = n & 31;
    float v = (ii < 31) ? W[((size_t)(t * 31 + ii)) * IN_DIM + k] : 0.f;
    uint32_t tv = f2tf32(v);
    int ntile = n >> 3, nr = n & 7, k8 = k >> 3, kc = k & 7;
    int lane = nr * 4 + (kc & 3);
    int reg = kc >> 2;                  // b0: k<4, b1: k>=4
    g_B[(((size_t)ntile * 64 + k8) * 32 + lane) * 2 + reg] = tv;
    if (k == 0) g_bp[n] = (ii < 31) ? b[t * 31 + ii] : 0.f;
}

// ---------------- fused GEMM (tf32 mma.sync) + routing kernel ----------------
__global__ __launch_bounds__(THREADS, 1)
void dndf_mma_kernel() {
    extern __shared__ char smem[];
    const uint32_t sb = smem_u32(smem);

    const int tid = threadIdx.x;
    const int wid = tid >> 5;
    const int lid = tid & 31;
    const int wm = wid & 3;          // 4 m-groups of 32 rows (2 mtiles)
    const int wn = wid >> 2;         // 4 n-groups of 32 cols (4 ntiles)
    const int bm8  = blockIdx.y * 8;    // first mtile of CTA
    const int bn16 = blockIdx.x * 16;   // first ntile of CTA
    const int mrow_base = blockIdx.y * BM;
    const int ncol_base = blockIdx.x * BN;

    float acc[2][4][4];
#pragma unroll
    for (int i = 0; i < 2; i++)
#pragma unroll
        for (int j = 0; j < 4; j++)
#pragma unroll
            for (int r = 0; r < 4; r++) acc[i][j][r] = 0.f;

    // ---- cp.async: one chunk = A 16KB + B 16KB, 4 x 16B per thread ----
    auto load_chunk = [&](int c, uint32_t st) {
#pragma unroll
        for (int it = 0; it < 4; it++) {
            int s = tid + it * THREADS;         // 0..2047
            if (s < 1024) {                     // A: mt = s>>7, 2KB contiguous per mtile
                int mt = s >> 7, off = (s & 127) << 4;
                const char* src = (const char*)g_A +
                    ((size_t)(bm8 + mt) * 64 + c * 4) * 512 + off;
                cp16(st + mt * 2048 + off, src);
            } else {                            // B: nt = (s-1024)>>6, 1KB per ntile
                int s2 = s - 1024;
                int nt = s2 >> 6, off = (s2 & 63) << 4;
                const char* src = (const char*)g_B +
                    ((size_t)(bn16 + nt) * 64 + c * 4) * 256 + off;
                cp16(st + A_STAGE_BYTES + nt * 1024 + off, src);
            }
        }
        asm volatile("cp.async.commit_group;" ::: "memory");
    };

    // prefetch chunks 0,1 into stages 0,1
    load_chunk(0, sb);
    load_chunk(1, sb + STAGE_BYTES);

    // fragment base offsets within a stage
    const uint32_t a_lane_off = (uint32_t)lid * 16;
    const uint32_t b_lane_off = A_STAGE_BYTES + (uint32_t)lid * 8;

    int s_cur = 0;   // stage of chunk c
#pragma unroll 1
    for (int c = 0; c < NKCH; c++) {
        asm volatile("cp.async.wait_group 1;" ::: "memory");
        __syncthreads();

        if (c + 2 < NKCH) {
            int s_nxt = s_cur + 2; if (s_nxt >= NSTAGE) s_nxt -= NSTAGE;
            load_chunk(c + 2, sb + s_nxt * STAGE_BYTES);
        } else {
            asm volatile("cp.async.commit_group;" ::: "memory");  // keep group count in step
        }

        const uint32_t st = sb + s_cur * STAGE_BYTES;
#pragma unroll
        for (int k8 = 0; k8 < 4; k8++) {
            uint32_t a[2][4], b[4][2];
#pragma unroll
            for (int mi = 0; mi < 2; mi++)
                lds128(a[mi][0], a[mi][1], a[mi][2], a[mi][3],
                       st + ((wm * 2 + mi) * 4 + k8) * 512 + a_lane_off);
#pragma unroll
            for (int nb = 0; nb < 4; nb++)
                lds64(b[nb][0], b[nb][1],
                      st + ((wn * 4 + nb) * 4 + k8) * 256 + b_lane_off);
#pragma unroll
            for (int mi = 0; mi < 2; mi++)
#pragma unroll
                for (int nb = 0; nb < 4; nb++)
                    mma_tf32(acc[mi][nb][0], acc[mi][nb][1], acc[mi][nb][2], acc[mi][nb][3],
                             a[mi][0], a[mi][1], a[mi][2], a[mi][3],
                             b[nb][0], b[nb][1]);
        }
        if (++s_cur >= NSTAGE) s_cur = 0;
    }

    asm volatile("cp.async.wait_group 0;" ::: "memory");
    __syncthreads();   // mainloop done; smem free for reuse

    // ---- stage bias + leaf tables ----
    float* p_s    = (float*)(smem + UOFF_P);
    float* lf_s   = (float*)(smem + UOFF_LF);
    float* bias_s = (float*)(smem + UOFF_BIAS);
    if (tid < 128) bias_s[tid] = g_bp[ncol_base + tid];
    {
        const float4* src = (const float4*)&g_leafs_sm[(size_t)(blockIdx.x * 4) * NL * ODIM];
        ((float4*)lf_s)[tid] = src[tid];   // 512 float4s, 512 threads
    }
    __syncthreads();

    // ---- sigmoid(acc + bias) -> p_s, tree-interleaved: p_s[row][node*4 + tree] ----
#pragma unroll
    for (int mi = 0; mi < 2; mi++) {
#pragma unroll
        for (int nb = 0; nb < 4; nb++) {
            const int colb = wn * 32 + nb * 8 + (lid & 3) * 2;
            const int rowb = wm * 32 + mi * 16 + (lid >> 2);
#pragma unroll
            for (int r = 0; r < 4; r++) {
                const int row = rowb + (r >> 1) * 8;
                const int col = colb + (r & 1);           // 0..127 = tree*32 + node
                const int icol = (col & 31) * 4 + (col >> 5);
                const float v = acc[mi][nb][r] + bias_s[col];
                p_s[row * P_PITCH + icol] = 1.0f / (1.0f + __expf(-v));
            }
        }
    }
    __syncthreads();

    // ---- routing + leaf contraction: 512 tasks, one per thread ----
    {
        const int t = lid & 3;
        const int row = wid * 8 + (lid >> 2);
        const float4* ls4 = (const float4*)&lf_s[(t * NL) * ODIM];
        const float* P = &p_s[row * P_PITCH + t];   // node i at P[i*4]

        float bb[4], cc[8], dd[16];
        {
            float p0 = P[0];
            float p1 = P[4], p2 = P[8];
            float s01 = p0 * p1;
            float s02 = p2 - p0 * p2;      // (1-p0)*p2
            bb[0] = s01;         bb[1] = p0 - s01;
            bb[2] = s02;         bb[3] = (1.0f - p0) - s02;
        }
#pragma unroll
        for (int q = 0; q < 4; q++) {
            float pv = P[(3 + q) * 4];
            float s = bb[q] * pv;
            cc[2 * q] = s; cc[2 * q + 1] = bb[q] - s;
        }
#pragma unroll
        for (int q = 0; q < 8; q++) {
            float pv = P[(7 + q) * 4];
            float s = cc[q] * pv;
            dd[2 * q] = s; dd[2 * q + 1] = cc[q] - s;
        }

        float oacc[ODIM];
#pragma unroll
        for (int o = 0; o < ODIM; o++) oacc[o] = 0.f;

#pragma unroll
        for (int q = 0; q < 16; q++) {
            float pv = P[(15 + q) * 4];
            float r0 = dd[q] * pv;
            float r1 = dd[q] - r0;
            {
                float4 v0 = ls4[(2 * q) * 4 + 0], v1 = ls4[(2 * q) * 4 + 1];
                float4 v2 = ls4[(2 * q) * 4 + 2], v3 = ls4[(2 * q) * 4 + 3];
                oacc[0]  = fmaf(r0, v0.x, oacc[0]);  oacc[1]  = fmaf(r0, v0.y, oacc[1]);
                oacc[2]  = fmaf(r0, v0.z, oacc[2]);  oacc[3]  = fmaf(r0, v0.w, oacc[3]);
                oacc[4]  = fmaf(r0, v1.x, oacc[4]);  oacc[5]  = fmaf(r0, v1.y, oacc[5]);
                oacc[6]  = fmaf(r0, v1.z, oacc[6]);  oacc[7]  = fmaf(r0, v1.w, oacc[7]);
                oacc[8]  = fmaf(r0, v2.x, oacc[8]);  oacc[9]  = fmaf(r0, v2.y, oacc[9]);
                oacc[10] = fmaf(r0, v2.z, oacc[10]); oacc[11] = fmaf(r0, v2.w, oacc[11]);
                oacc[12] = fmaf(r0, v3.x, oacc[12]); oacc[13] = fmaf(r0, v3.y, oacc[13]);
                oacc[14] = fmaf(r0, v3.z, oacc[14]); oacc[15] = fmaf(r0, v3.w, oacc[15]);
            }
            {
                float4 v0 = ls4[(2 * q + 1) * 4 + 0], v1 = ls4[(2 * q + 1) * 4 + 1];
                float4 v2 = ls4[(2 * q + 1) * 4 + 2], v3 = ls4[(2 * q + 1) * 4 + 3];
                oacc[0]  = fmaf(r1, v0.x, oacc[0]);  oacc[1]  = fmaf(r1, v0.y, oacc[1]);
                oacc[2]  = fmaf(r1, v0.z, oacc[2]);  oacc[3]  = fmaf(r1, v0.w, oacc[3]);
                oacc[4]  = fmaf(r1, v1.x, oacc[4]);  oacc[5]  = fmaf(r1, v1.y, oacc[5]);
                oacc[6]  = fmaf(r1, v1.z, oacc[6]);  oacc[7]  = fmaf(r1, v1.w, oacc[7]);
                oacc[8]  = fmaf(r1, v2.x, oacc[8]);  oacc[9]  = fmaf(r1, v2.y, oacc[9]);
                oacc[10] = fmaf(r1, v2.z, oacc[10]); oacc[11] = fmaf(r1, v2.w, oacc[11]);
                oacc[12] = fmaf(r1, v3.x, oacc[12]); oacc[13] = fmaf(r1, v3.y, oacc[13]);
                oacc[14] = fmaf(r1, v3.z, oacc[14]); oacc[15] = fmaf(r1, v3.w, oacc[15]);
            }
        }

        // sum the 4 trees of this row (lane-quad butterfly)
#pragma unroll
        for (int o = 0; o < ODIM; o++) {
            oacc[o] += __shfl_xor_sync(0xffffffffu, oacc[o], 1);
            oacc[o] += __shfl_xor_sync(0xffffffffu, oacc[o], 2);
        }
        // all 4 lanes hold the row sum; lane t writes float4 quarter t
        float4 v = make_float4(oacc[t * 4 + 0], oacc[t * 4 + 1],
                               oacc[t * 4 + 2], oacc[t * 4 + 3]);
        *(float4*)&g_outp[((size_t)blockIdx.x * BATCH + mrow_base + row) * ODIM + t * 4] = v;
    }
}

// ---------------- final reduce over the 16 N-groups ----------------
__global__ void reduce_kernel(float* __restrict__ out) {
    int i = blockIdx.x * blockDim.x + threadIdx.x;   // 32768 float4s
    float4 acc = make_float4(0.f, 0.f, 0.f, 0.f);
#pragma unroll
    for (int g = 0; g < NGRP; g++) {
        float4 v = ((const float4*)g_outp)[(size_t)g * (BATCH * 4) + i];
        acc.x += v.x; acc.y += v.y; acc.z += v.z; acc.w += v.w;
    }
    const float s = 1.0f / NUM_TREE;
    ((float4*)out)[i] = make_float4(acc.x * s, acc.y * s, acc.z * s, acc.w * s);
}

// ---------------- launch ----------------
extern "C" void kernel_launch(void* const* d_in, const int* in_sizes, int n_in,
                              void* d_out, int out_size) {
    const float* x     = (const float*)d_in[0];   // [8192, 512]
    const float* W     = (const float*)d_in[1];   // [1984, 512]
    const float* b     = (const float*)d_in[2];   // [1984]
    const float* leafs = (const float*)d_in[3];   // [64, 32, 16]
    float* out = (float*)d_out;                   // [8192, 16]

    leafs_softmax_kernel<<<(NUM_TREE * NL + 255) / 256, 256>>>(leafs);
    prep_x_kernel<<<(BATCH * IN_DIM) / 256, 256>>>(x);
    prep_w_kernel<<<(2048 * IN_DIM) / 256, 256>>>(W, b);

    cudaFuncSetAttribute(dndf_mma_kernel,
                         cudaFuncAttributeMaxDynamicSharedMemorySize, SMEM_TOTAL);
    dndf_mma_kernel<<<dim3(NGRP, BATCH / BM), THREADS, SMEM_TOTAL>>>();

    reduce_kernel<<<(BATCH * 4) / 256, 256>>>(out);
}